// round 1
// baseline (speedup 1.0000x reference)
#include <cuda_runtime.h>
#include <cuda_bf16.h>
#include <cstdint>

#define N 8192
#define D 128
#define CHUNKS 8
#define TILES_PER_CHUNK (N / 128 / CHUNKS)   // 8
#define LDS 136   // padded smem row stride in bf16 elems (272 B -> conflict-free ldmatrix)

// log2(e) / 0.07
#define EXP_SCALE 20.60992915555662f

__device__ __nv_bfloat16 g_fn[N * D];
__device__ float g_posP[CHUNKS * N];
__device__ float g_negP[CHUNKS * N];

__device__ __forceinline__ float ex2f(float x) {
    float y;
    asm("ex2.approx.ftz.f32 %0, %1;" : "=f"(y) : "f"(x));
    return y;
}

__device__ __forceinline__ void mma16816(float d[4], const uint32_t a[4],
                                         uint32_t b0, uint32_t b1) {
    asm volatile(
        "mma.sync.aligned.m16n8k16.row.col.f32.bf16.bf16.f32 "
        "{%0,%1,%2,%3}, {%4,%5,%6,%7}, {%8,%9}, {%0,%1,%2,%3};"
        : "+f"(d[0]), "+f"(d[1]), "+f"(d[2]), "+f"(d[3])
        : "r"(a[0]), "r"(a[1]), "r"(a[2]), "r"(a[3]), "r"(b0), "r"(b1));
}

// ---------------------------------------------------------------------------
// Kernel 1: L2-normalize rows of features, write bf16. One warp per row.
// ---------------------------------------------------------------------------
__global__ void normalize_kernel(const float* __restrict__ f) {
    int warp = threadIdx.x >> 5, lane = threadIdx.x & 31;
    int row = blockIdx.x * 8 + warp;
    const float4 v = ((const float4*)(f + (size_t)row * D))[lane];
    float ss = v.x * v.x + v.y * v.y + v.z * v.z + v.w * v.w;
#pragma unroll
    for (int o = 16; o > 0; o >>= 1) ss += __shfl_xor_sync(0xffffffffu, ss, o);
    float rinv = 1.0f / fmaxf(sqrtf(ss), 1e-8f);
    union { __nv_bfloat16 h[4]; uint2 u; } pack;
    pack.h[0] = __float2bfloat16_rn(v.x * rinv);
    pack.h[1] = __float2bfloat16_rn(v.y * rinv);
    pack.h[2] = __float2bfloat16_rn(v.z * rinv);
    pack.h[3] = __float2bfloat16_rn(v.w * rinv);
    ((uint2*)(g_fn + (size_t)row * D))[lane] = pack.u;
}

// ---------------------------------------------------------------------------
// Kernel 2: fused Gram-tile GEMM (bf16 mma.sync) + exp + masked row-sums.
// Grid: (N/128 row tiles, CHUNKS col chunks). Block: 256 threads (8 warps).
// Warp w owns rows [m0 + 16w, m0 + 16w + 16). A-frags live in registers.
// ---------------------------------------------------------------------------
__global__ __launch_bounds__(256) void simloss_kernel(const int* __restrict__ pm,
                                                      const int* __restrict__ nm) {
    __shared__ __align__(16) __nv_bfloat16 Bs[128 * LDS];
    const int tid = threadIdx.x;
    const int w = tid >> 5, l = tid & 31;
    const int m0 = blockIdx.x * 128;
    const int chunk = blockIdx.y;

    const uint32_t base = (uint32_t)__cvta_generic_to_shared(Bs);

    // ---- load A tile (rows m0..m0+127) into smem, then extract frags ----
    {
        const uint4* src = (const uint4*)(g_fn + (size_t)m0 * D);
#pragma unroll
        for (int i = 0; i < 8; i++) {
            int idx = tid + i * 256;
            int r = idx >> 4, c = idx & 15;
            *(uint4*)(Bs + r * LDS + c * 8) = src[r * 16 + c];
        }
    }
    __syncthreads();

    uint32_t a[8][4];
    {
        int ar = w * 16 + (l & 15);
        int ac = (l >> 4) * 8;
#pragma unroll
        for (int ks = 0; ks < 8; ks++) {
            uint32_t addr = base + (uint32_t)((ar * LDS + ks * 16 + ac) * 2);
            asm volatile(
                "ldmatrix.sync.aligned.m8n8.x4.shared.b16 {%0,%1,%2,%3}, [%4];"
                : "=r"(a[ks][0]), "=r"(a[ks][1]), "=r"(a[ks][2]), "=r"(a[ks][3])
                : "r"(addr));
        }
    }

    float posAcc0 = 0.f, posAcc1 = 0.f, negAcc0 = 0.f, negAcc1 = 0.f;
    const int gr0 = m0 + w * 16 + (l >> 2);
    const int gr1 = gr0 + 8;

    const int brow = (l >> 4) * 8 + (l & 7);
    const int bcol = ((l >> 3) & 1) * 8;

    for (int t = 0; t < TILES_PER_CHUNK; t++) {
        const int j0 = (chunk * TILES_PER_CHUNK + t) * 128;
        __syncthreads();   // everyone done reading Bs from previous iter
        {
            const uint4* src = (const uint4*)(g_fn + (size_t)j0 * D);
#pragma unroll
            for (int i = 0; i < 8; i++) {
                int idx = tid + i * 256;
                int r = idx >> 4, c = idx & 15;
                *(uint4*)(Bs + r * LDS + c * 8) = src[r * 16 + c];
            }
        }
        __syncthreads();

        float acc[16][4];
#pragma unroll
        for (int i = 0; i < 16; i++) {
            acc[i][0] = 0.f; acc[i][1] = 0.f; acc[i][2] = 0.f; acc[i][3] = 0.f;
        }

#pragma unroll
        for (int ks = 0; ks < 8; ks++) {
#pragma unroll
            for (int nf2 = 0; nf2 < 8; nf2++) {
                uint32_t addr =
                    base + (uint32_t)(((nf2 * 16 + brow) * LDS + ks * 16 + bcol) * 2);
                uint32_t b0, b1, b2, b3;
                asm volatile(
                    "ldmatrix.sync.aligned.m8n8.x4.shared.b16 {%0,%1,%2,%3}, [%4];"
                    : "=r"(b0), "=r"(b1), "=r"(b2), "=r"(b3)
                    : "r"(addr));
                mma16816(acc[nf2 * 2], a[ks], b0, b1);
                mma16816(acc[nf2 * 2 + 1], a[ks], b2, b3);
            }
        }

        // ---- epilogue: exp + masked accumulation ----
        const bool diag = (j0 == m0);
#pragma unroll
        for (int nf = 0; nf < 16; nf++) {
            int jc = j0 + nf * 8 + (l & 3) * 2;
            int2 P0 = *(const int2*)(pm + (size_t)gr0 * N + jc);
            int2 Q0 = *(const int2*)(nm + (size_t)gr0 * N + jc);
            int2 P1 = *(const int2*)(pm + (size_t)gr1 * N + jc);
            int2 Q1 = *(const int2*)(nm + (size_t)gr1 * N + jc);
            if (diag) {
                if (gr0 == jc)     { P0.x = 0; Q0.x = 0; }
                if (gr0 == jc + 1) { P0.y = 0; Q0.y = 0; }
                if (gr1 == jc)     { P1.x = 0; Q1.x = 0; }
                if (gr1 == jc + 1) { P1.y = 0; Q1.y = 0; }
            }
            float e00 = ex2f(acc[nf][0] * EXP_SCALE);
            float e01 = ex2f(acc[nf][1] * EXP_SCALE);
            float e10 = ex2f(acc[nf][2] * EXP_SCALE);
            float e11 = ex2f(acc[nf][3] * EXP_SCALE);
            posAcc0 += e00 * (float)P0.x + e01 * (float)P0.y;
            negAcc0 += e00 * (float)Q0.x + e01 * (float)Q0.y;
            posAcc1 += e10 * (float)P1.x + e11 * (float)P1.y;
            negAcc1 += e10 * (float)Q1.x + e11 * (float)Q1.y;
        }
    }

    // ---- reduce across the 4 lanes that share a row (l & 3) ----
#pragma unroll
    for (int o = 1; o < 4; o <<= 1) {
        posAcc0 += __shfl_xor_sync(0xffffffffu, posAcc0, o);
        posAcc1 += __shfl_xor_sync(0xffffffffu, posAcc1, o);
        negAcc0 += __shfl_xor_sync(0xffffffffu, negAcc0, o);
        negAcc1 += __shfl_xor_sync(0xffffffffu, negAcc1, o);
    }
    if ((l & 3) == 0) {
        g_posP[chunk * N + gr0] = posAcc0;
        g_posP[chunk * N + gr1] = posAcc1;
        g_negP[chunk * N + gr0] = negAcc0;
        g_negP[chunk * N + gr1] = negAcc1;
    }
}

// ---------------------------------------------------------------------------
// Kernel 3: final loss reduction. One block.
// ---------------------------------------------------------------------------
__global__ void loss_kernel(float* __restrict__ out) {
    __shared__ double sred[32];
    double s = 0.0;
    for (int r = threadIdx.x; r < N; r += blockDim.x) {
        float pos = 0.f, neg = 0.f;
#pragma unroll
        for (int c = 0; c < CHUNKS; c++) {
            pos += g_posP[c * N + r];
            neg += g_negP[c * N + r];
        }
        s += (double)logf(pos / (pos + neg));
    }
#pragma unroll
    for (int o = 16; o > 0; o >>= 1) s += __shfl_xor_sync(0xffffffffu, s, o);
    int warp = threadIdx.x >> 5, lane = threadIdx.x & 31;
    if (lane == 0) sred[warp] = s;
    __syncthreads();
    if (warp == 0) {
        s = (lane < (int)(blockDim.x >> 5)) ? sred[lane] : 0.0;
#pragma unroll
        for (int o = 16; o > 0; o >>= 1) s += __shfl_xor_sync(0xffffffffu, s, o);
        if (lane == 0) out[0] = (float)(-s / (double)N);
    }
}

extern "C" void kernel_launch(void* const* d_in, const int* in_sizes, int n_in,
                              void* d_out, int out_size) {
    const float* features = (const float*)d_in[0];
    const int* pos_mask = (const int*)d_in[1];
    const int* neg_mask = (const int*)d_in[2];
    float* out = (float*)d_out;

    normalize_kernel<<<N / 8, 256>>>(features);
    simloss_kernel<<<dim3(N / 128, CHUNKS), 256>>>(pos_mask, neg_mask);
    loss_kernel<<<1, 1024>>>(out);
}

// round 2
// speedup vs baseline: 1.0733x; 1.0733x over previous
#include <cuda_runtime.h>
#include <cuda_bf16.h>
#include <cstdint>

#define N 8192
#define D 128
#define CHUNKS 8
#define TILES_PER_CHUNK (N / 128 / CHUNKS)   // 8
#define LDS 136   // padded smem row stride in bf16 elems (272 B -> conflict-free ldmatrix)

// log2(e) / 0.07
#define EXP_SCALE 20.60992915555662f

__device__ __nv_bfloat16 g_fn[N * D];
__device__ float g_posP[CHUNKS * N];
__device__ float g_negP[CHUNKS * N];

__device__ __forceinline__ float ex2f(float x) {
    float y;
    asm("ex2.approx.ftz.f32 %0, %1;" : "=f"(y) : "f"(x));
    return y;
}

__device__ __forceinline__ void prefetch_l2(const void* p) {
    asm volatile("prefetch.global.L2 [%0];" :: "l"(p));
}

__device__ __forceinline__ void mma16816(float d[4], const uint32_t a[4],
                                         uint32_t b0, uint32_t b1) {
    asm volatile(
        "mma.sync.aligned.m16n8k16.row.col.f32.bf16.bf16.f32 "
        "{%0,%1,%2,%3}, {%4,%5,%6,%7}, {%8,%9}, {%0,%1,%2,%3};"
        : "+f"(d[0]), "+f"(d[1]), "+f"(d[2]), "+f"(d[3])
        : "r"(a[0]), "r"(a[1]), "r"(a[2]), "r"(a[3]), "r"(b0), "r"(b1));
}

// async 16B copy of one 128x128 bf16 tile (row-major, D=128) into padded smem
__device__ __forceinline__ void copy_tile_async(uint32_t sbase,
                                                const __nv_bfloat16* __restrict__ src,
                                                int tid) {
#pragma unroll
    for (int i = 0; i < 8; i++) {
        int idx = tid + i * 256;
        int r = idx >> 4, c = idx & 15;
        uint32_t dst = sbase + (uint32_t)((r * LDS + c * 8) * 2);
        const void* s = src + (size_t)r * D + c * 8;
        asm volatile("cp.async.cg.shared.global [%0], [%1], 16;"
                     :: "r"(dst), "l"(s));
    }
}

// prefetch both masks' 128x128 int32 tile (1024 x 128B lines) into L2
__device__ __forceinline__ void prefetch_mask_tile(const int* __restrict__ pm,
                                                   const int* __restrict__ nm,
                                                   int m0, int j0, int tid) {
#pragma unroll
    for (int i = 0; i < 4; i++) {
        int L = tid + i * 256;
        const int* msk = (L & 512) ? nm : pm;
        int r = (L >> 2) & 127;
        int seg = L & 3;
        prefetch_l2(msk + (size_t)(m0 + r) * N + j0 + seg * 32);
    }
}

// ---------------------------------------------------------------------------
// Kernel 1: L2-normalize rows of features, write bf16. One warp per row.
// ---------------------------------------------------------------------------
__global__ void normalize_kernel(const float* __restrict__ f) {
    int warp = threadIdx.x >> 5, lane = threadIdx.x & 31;
    int row = blockIdx.x * 8 + warp;
    const float4 v = ((const float4*)(f + (size_t)row * D))[lane];
    float ss = v.x * v.x + v.y * v.y + v.z * v.z + v.w * v.w;
#pragma unroll
    for (int o = 16; o > 0; o >>= 1) ss += __shfl_xor_sync(0xffffffffu, ss, o);
    float rinv = 1.0f / fmaxf(sqrtf(ss), 1e-8f);
    union { __nv_bfloat16 h[4]; uint2 u; } pack;
    pack.h[0] = __float2bfloat16_rn(v.x * rinv);
    pack.h[1] = __float2bfloat16_rn(v.y * rinv);
    pack.h[2] = __float2bfloat16_rn(v.z * rinv);
    pack.h[3] = __float2bfloat16_rn(v.w * rinv);
    ((uint2*)(g_fn + (size_t)row * D))[lane] = pack.u;
}

// ---------------------------------------------------------------------------
// Kernel 2: fused Gram-tile GEMM (bf16 mma.sync) + exp + masked row-sums.
// Double-buffered cp.async B tiles + L2 mask prefetch for full overlap.
// Grid: (N/128 row tiles, CHUNKS col chunks). Block: 256 threads (8 warps).
// ---------------------------------------------------------------------------
__global__ __launch_bounds__(256, 2) void simloss_kernel(const int* __restrict__ pm,
                                                         const int* __restrict__ nm) {
    __shared__ __align__(16) __nv_bfloat16 Bs[2][128 * LDS];
    const int tid = threadIdx.x;
    const int w = tid >> 5, l = tid & 31;
    const int m0 = blockIdx.x * 128;
    const int chunk = blockIdx.y;
    const int j_base = chunk * TILES_PER_CHUNK * 128;

    const uint32_t base0 = (uint32_t)__cvta_generic_to_shared(Bs[0]);
    const uint32_t base1 = (uint32_t)__cvta_generic_to_shared(Bs[1]);

    // warm L2 with tile 0's masks as early as possible
    prefetch_mask_tile(pm, nm, m0, j_base, tid);

    // A tile -> buf0, B tile0 -> buf1 (both async)
    copy_tile_async(base0, g_fn + (size_t)m0 * D, tid);
    asm volatile("cp.async.commit_group;");
    copy_tile_async(base1, g_fn + (size_t)j_base * D, tid);
    asm volatile("cp.async.commit_group;");

    asm volatile("cp.async.wait_group 1;");   // A tile ready
    __syncthreads();

    // ---- extract A frags from buf0 ----
    uint32_t a[8][4];
    {
        int ar = w * 16 + (l & 15);
        int ac = (l >> 4) * 8;
#pragma unroll
        for (int ks = 0; ks < 8; ks++) {
            uint32_t addr = base0 + (uint32_t)((ar * LDS + ks * 16 + ac) * 2);
            asm volatile(
                "ldmatrix.sync.aligned.m8n8.x4.shared.b16 {%0,%1,%2,%3}, [%4];"
                : "=r"(a[ks][0]), "=r"(a[ks][1]), "=r"(a[ks][2]), "=r"(a[ks][3])
                : "r"(addr));
        }
    }

    float posAcc0 = 0.f, posAcc1 = 0.f, negAcc0 = 0.f, negAcc1 = 0.f;
    const int gr0 = m0 + w * 16 + (l >> 2);
    const int gr1 = gr0 + 8;

    const int brow = (l >> 4) * 8 + (l & 7);
    const int bcol = ((l >> 3) & 1) * 8;

    for (int t = 0; t < TILES_PER_CHUNK; t++) {
        const int j0 = j_base + t * 128;
        asm volatile("cp.async.wait_group 0;");   // tile t's B copy done
        __syncthreads();                          // + all warps done with prev buf

        const uint32_t cur = (t & 1) ? base0 : base1;
        const uint32_t nxt = (t & 1) ? base1 : base0;

        if (t + 1 < TILES_PER_CHUNK) {
            // kick off next B tile copy + next mask prefetch; drains during MMA/epilogue
            copy_tile_async(nxt, g_fn + (size_t)(j0 + 128) * D, tid);
            asm volatile("cp.async.commit_group;");
            prefetch_mask_tile(pm, nm, m0, j0 + 128, tid);
        }

        float acc[16][4];
#pragma unroll
        for (int i = 0; i < 16; i++) {
            acc[i][0] = 0.f; acc[i][1] = 0.f; acc[i][2] = 0.f; acc[i][3] = 0.f;
        }

#pragma unroll
        for (int ks = 0; ks < 8; ks++) {
#pragma unroll
            for (int nf2 = 0; nf2 < 8; nf2++) {
                uint32_t addr =
                    cur + (uint32_t)(((nf2 * 16 + brow) * LDS + ks * 16 + bcol) * 2);
                uint32_t b0, b1, b2, b3;
                asm volatile(
                    "ldmatrix.sync.aligned.m8n8.x4.shared.b16 {%0,%1,%2,%3}, [%4];"
                    : "=r"(b0), "=r"(b1), "=r"(b2), "=r"(b3)
                    : "r"(addr));
                mma16816(acc[nf2 * 2], a[ks], b0, b1);
                mma16816(acc[nf2 * 2 + 1], a[ks], b2, b3);
            }
        }

        // ---- epilogue: exp + masked accumulation (masks are L2-warm) ----
        const bool diag = (j0 == m0);
#pragma unroll
        for (int nf = 0; nf < 16; nf++) {
            int jc = j0 + nf * 8 + (l & 3) * 2;
            int2 P0 = *(const int2*)(pm + (size_t)gr0 * N + jc);
            int2 Q0 = *(const int2*)(nm + (size_t)gr0 * N + jc);
            int2 P1 = *(const int2*)(pm + (size_t)gr1 * N + jc);
            int2 Q1 = *(const int2*)(nm + (size_t)gr1 * N + jc);
            if (diag) {
                if (gr0 == jc)     { P0.x = 0; Q0.x = 0; }
                if (gr0 == jc + 1) { P0.y = 0; Q0.y = 0; }
                if (gr1 == jc)     { P1.x = 0; Q1.x = 0; }
                if (gr1 == jc + 1) { P1.y = 0; Q1.y = 0; }
            }
            float e00 = ex2f(acc[nf][0] * EXP_SCALE);
            float e01 = ex2f(acc[nf][1] * EXP_SCALE);
            float e10 = ex2f(acc[nf][2] * EXP_SCALE);
            float e11 = ex2f(acc[nf][3] * EXP_SCALE);
            posAcc0 += e00 * (float)P0.x + e01 * (float)P0.y;
            negAcc0 += e00 * (float)Q0.x + e01 * (float)Q0.y;
            posAcc1 += e10 * (float)P1.x + e11 * (float)P1.y;
            negAcc1 += e10 * (float)Q1.x + e11 * (float)Q1.y;
        }
    }

    // ---- reduce across the 4 lanes that share a row (l & 3) ----
#pragma unroll
    for (int o = 1; o < 4; o <<= 1) {
        posAcc0 += __shfl_xor_sync(0xffffffffu, posAcc0, o);
        posAcc1 += __shfl_xor_sync(0xffffffffu, posAcc1, o);
        negAcc0 += __shfl_xor_sync(0xffffffffu, negAcc0, o);
        negAcc1 += __shfl_xor_sync(0xffffffffu, negAcc1, o);
    }
    if ((l & 3) == 0) {
        g_posP[chunk * N + gr0] = posAcc0;
        g_posP[chunk * N + gr1] = posAcc1;
        g_negP[chunk * N + gr0] = negAcc0;
        g_negP[chunk * N + gr1] = negAcc1;
    }
}

// ---------------------------------------------------------------------------
// Kernel 3: final loss reduction. One block.
// ---------------------------------------------------------------------------
__global__ void loss_kernel(float* __restrict__ out) {
    __shared__ double sred[32];
    double s = 0.0;
    for (int r = threadIdx.x; r < N; r += blockDim.x) {
        float pos = 0.f, neg = 0.f;
#pragma unroll
        for (int c = 0; c < CHUNKS; c++) {
            pos += g_posP[c * N + r];
            neg += g_negP[c * N + r];
        }
        s += (double)logf(pos / (pos + neg));
    }
#pragma unroll
    for (int o = 16; o > 0; o >>= 1) s += __shfl_xor_sync(0xffffffffu, s, o);
    int warp = threadIdx.x >> 5, lane = threadIdx.x & 31;
    if (lane == 0) sred[warp] = s;
    __syncthreads();
    if (warp == 0) {
        s = (lane < (int)(blockDim.x >> 5)) ? sred[lane] : 0.0;
#pragma unroll
        for (int o = 16; o > 0; o >>= 1) s += __shfl_xor_sync(0xffffffffu, s, o);
        if (lane == 0) out[0] = (float)(-s / (double)N);
    }
}

extern "C" void kernel_launch(void* const* d_in, const int* in_sizes, int n_in,
                              void* d_out, int out_size) {
    const float* features = (const float*)d_in[0];
    const int* pos_mask = (const int*)d_in[1];
    const int* neg_mask = (const int*)d_in[2];
    float* out = (float*)d_out;

    normalize_kernel<<<N / 8, 256>>>(features);
    simloss_kernel<<<dim3(N / 128, CHUNKS), 256>>>(pos_mask, neg_mask);
    loss_kernel<<<1, 1024>>>(out);
}

// round 4
// speedup vs baseline: 1.2946x; 1.2062x over previous
#include <cuda_runtime.h>
#include <cuda_bf16.h>
#include <cstdint>

#define N 8192
#define D 128
#define NT 64              // 128-wide tiles per dimension
#define NPAIRS 2080        // NT*(NT+1)/2 upper-triangular tile pairs
#define LDS 136            // padded smem row stride (bf16) for feature tiles
#define FN_SCALE 4.539815982f   // sqrt(log2(e)/0.07), folded exp scale

// smem layout (bytes): As/eT overlay [0,34816), Bs [34816,69632)
#define AS_OFF 0u
#define BS_OFF 34816u
#define SMEM_BYTES 69632

__device__ __nv_bfloat16 g_fn[N * D];
__device__ float g_pos[N];
__device__ float g_neg[N];

__device__ __forceinline__ float ex2f(float x) {
    float y;
    asm("ex2.approx.ftz.f32 %0, %1;" : "=f"(y) : "f"(x));
    return y;
}

__device__ __forceinline__ void prefetch_l2(const void* p) {
    asm volatile("prefetch.global.L2 [%0];" :: "l"(p));
}

__device__ __forceinline__ void mma16816(float d[4], const uint32_t a[4],
                                         uint32_t b0, uint32_t b1) {
    asm volatile(
        "mma.sync.aligned.m16n8k16.row.col.f32.bf16.bf16.f32 "
        "{%0,%1,%2,%3}, {%4,%5,%6,%7}, {%8,%9}, {%0,%1,%2,%3};"
        : "+f"(d[0]), "+f"(d[1]), "+f"(d[2]), "+f"(d[3])
        : "r"(a[0]), "r"(a[1]), "r"(a[2]), "r"(a[3]), "r"(b0), "r"(b1));
}

// async copy of one 128x128 bf16 tile (row-major, D=128) into padded smem
__device__ __forceinline__ void copy_tile_async(uint32_t sbase,
                                                const __nv_bfloat16* __restrict__ src,
                                                int tid) {
#pragma unroll
    for (int i = 0; i < 8; i++) {
        int idx = tid + i * 256;
        int r = idx >> 4, c = idx & 15;
        uint32_t dst = sbase + (uint32_t)((r * LDS + c * 8) * 2);
        const void* s = src + (size_t)r * D + c * 8;
        asm volatile("cp.async.cg.shared.global [%0], [%1], 16;"
                     :: "r"(dst), "l"(s));
    }
}

// L2-prefetch both masks' 128x128 int32 block at (rows m0, cols c0)
__device__ __forceinline__ void prefetch_mask_block(const int* __restrict__ pm,
                                                    const int* __restrict__ nm,
                                                    int m0, int c0, int tid) {
#pragma unroll
    for (int i = 0; i < 4; i++) {
        int L = tid + i * 256;
        const int* msk = (L & 512) ? nm : pm;
        int r = (L >> 2) & 127;
        int seg = L & 3;
        prefetch_l2(msk + (size_t)(m0 + r) * N + c0 + seg * 32);
    }
}

// ---------------------------------------------------------------------------
// Kernel 1: L2-normalize rows (scale folded) + zero the accumulators.
// ---------------------------------------------------------------------------
__global__ void normalize_kernel(const float* __restrict__ f) {
    int z = blockIdx.x * 256 + threadIdx.x;
    if (z < N) g_pos[z] = 0.f;
    else if (z < 2 * N) g_neg[z - N] = 0.f;

    int warp = threadIdx.x >> 5, lane = threadIdx.x & 31;
    int row = blockIdx.x * 8 + warp;
    const float4 v = ((const float4*)(f + (size_t)row * D))[lane];
    float ss = v.x * v.x + v.y * v.y + v.z * v.z + v.w * v.w;
#pragma unroll
    for (int o = 16; o > 0; o >>= 1) ss += __shfl_xor_sync(0xffffffffu, ss, o);
    float rinv = FN_SCALE / fmaxf(sqrtf(ss), 1e-8f);
    union { __nv_bfloat16 h[4]; uint2 u; } pack;
    pack.h[0] = __float2bfloat16_rn(v.x * rinv);
    pack.h[1] = __float2bfloat16_rn(v.y * rinv);
    pack.h[2] = __float2bfloat16_rn(v.z * rinv);
    pack.h[3] = __float2bfloat16_rn(v.w * rinv);
    ((uint2*)(g_fn + (size_t)row * D))[lane] = pack.u;
}

// ---------------------------------------------------------------------------
// Kernel 2: symmetric Gram tile (upper triangle only). One 128x128 tile pair
// per CTA. Pass 1: rows in I with masks (I,J). Pass 2 (off-diag): rows in J
// with masks (J,I), exp values re-read from transposed bf16 smem tile.
// ---------------------------------------------------------------------------
__global__ __launch_bounds__(256, 2) void simloss_sym(const int* __restrict__ pm,
                                                      const int* __restrict__ nm) {
    extern __shared__ __align__(16) char smem[];
    const uint32_t base = (uint32_t)__cvta_generic_to_shared(smem);
    const int tid = threadIdx.x;
    const int w = tid >> 5, l = tid & 31;

    // ---- decode triangular pair index ----
    int k = blockIdx.x;
    int I = (int)((129.0f - sqrtf(16641.0f - 8.0f * (float)k)) * 0.5f);
    while ((I * (129 - I)) / 2 > k) I--;
    while (((I + 1) * (128 - I)) / 2 <= k) I++;
    const int J = I + (k - (I * (129 - I)) / 2);
    const int m0 = I * 128, j0 = J * 128;
    const bool isDiag = (I == J);

    // ---- start mask DRAM stream + feature tile copies ----
    prefetch_mask_block(pm, nm, m0, j0, tid);
    if (!isDiag) prefetch_mask_block(pm, nm, j0, m0, tid);

    copy_tile_async(base + AS_OFF, g_fn + (size_t)m0 * D, tid);
    copy_tile_async(base + BS_OFF, g_fn + (size_t)j0 * D, tid);
    asm volatile("cp.async.commit_group;");
    asm volatile("cp.async.wait_group 0;");
    __syncthreads();

    // ---- extract A frags from As ----
    uint32_t a[8][4];
    {
        int ar = w * 16 + (l & 15);
        int ac = (l >> 4) * 8;
#pragma unroll
        for (int ks = 0; ks < 8; ks++) {
            uint32_t addr = base + AS_OFF + (uint32_t)((ar * LDS + ks * 16 + ac) * 2);
            asm volatile(
                "ldmatrix.sync.aligned.m8n8.x4.shared.b16 {%0,%1,%2,%3}, [%4];"
                : "=r"(a[ks][0]), "=r"(a[ks][1]), "=r"(a[ks][2]), "=r"(a[ks][3])
                : "r"(addr));
        }
    }
    __syncthreads();   // all warps done with As before eT overlays it

    // ---- MMA: 128x128x128 ----
    float acc[16][4];
#pragma unroll
    for (int i = 0; i < 16; i++) {
        acc[i][0] = 0.f; acc[i][1] = 0.f; acc[i][2] = 0.f; acc[i][3] = 0.f;
    }
    const int brow = (l >> 4) * 8 + (l & 7);
    const int bcol = ((l >> 3) & 1) * 8;
#pragma unroll
    for (int ks = 0; ks < 8; ks++) {
#pragma unroll
        for (int nf2 = 0; nf2 < 8; nf2++) {
            uint32_t addr = base + BS_OFF +
                            (uint32_t)(((nf2 * 16 + brow) * LDS + ks * 16 + bcol) * 2);
            uint32_t b0, b1, b2, b3;
            asm volatile(
                "ldmatrix.sync.aligned.m8n8.x4.shared.b16 {%0,%1,%2,%3}, [%4];"
                : "=r"(b0), "=r"(b1), "=r"(b2), "=r"(b3)
                : "r"(addr));
            mma16816(acc[nf2 * 2], a[ks], b0, b1);
            mma16816(acc[nf2 * 2 + 1], a[ks], b2, b3);
        }
    }

    // ---- pass 1: rows in I, masks (I,J); store eT for pass 2 ----
    char* eT = smem;                              // overlays As, stride 272 B
    const int il0 = w * 16 + (l >> 2), il1 = il0 + 8;
    const int gr0 = m0 + il0, gr1 = m0 + il1;
    float posAcc0 = 0.f, posAcc1 = 0.f, negAcc0 = 0.f, negAcc1 = 0.f;

#pragma unroll
    for (int nf = 0; nf < 16; nf++) {
        int jcl = nf * 8 + (l & 3) * 2;
        int jc = j0 + jcl;
        int2 P0 = *(const int2*)(pm + (size_t)gr0 * N + jc);
        int2 Q0 = *(const int2*)(nm + (size_t)gr0 * N + jc);
        int2 P1 = *(const int2*)(pm + (size_t)gr1 * N + jc);
        int2 Q1 = *(const int2*)(nm + (size_t)gr1 * N + jc);

        float e00 = ex2f(acc[nf][0]);
        float e01 = ex2f(acc[nf][1]);
        float e10 = ex2f(acc[nf][2]);
        float e11 = ex2f(acc[nf][3]);

        if (!isDiag) {
            *(__nv_bfloat16*)(eT + (size_t)jcl * 272 + il0 * 2) = __float2bfloat16_rn(e00);
            *(__nv_bfloat16*)(eT + (size_t)(jcl + 1) * 272 + il0 * 2) = __float2bfloat16_rn(e01);
            *(__nv_bfloat16*)(eT + (size_t)jcl * 272 + il1 * 2) = __float2bfloat16_rn(e10);
            *(__nv_bfloat16*)(eT + (size_t)(jcl + 1) * 272 + il1 * 2) = __float2bfloat16_rn(e11);
        } else {
            if (gr0 == jc)     { P0.x = 0; Q0.x = 0; }
            if (gr0 == jc + 1) { P0.y = 0; Q0.y = 0; }
            if (gr1 == jc)     { P1.x = 0; Q1.x = 0; }
            if (gr1 == jc + 1) { P1.y = 0; Q1.y = 0; }
        }
        posAcc0 = fmaf(e00, (float)P0.x, fmaf(e01, (float)P0.y, posAcc0));
        negAcc0 = fmaf(e00, (float)Q0.x, fmaf(e01, (float)Q0.y, negAcc0));
        posAcc1 = fmaf(e10, (float)P1.x, fmaf(e11, (float)P1.y, posAcc1));
        negAcc1 = fmaf(e10, (float)Q1.x, fmaf(e11, (float)Q1.y, negAcc1));
    }

#pragma unroll
    for (int o = 1; o < 4; o <<= 1) {
        posAcc0 += __shfl_xor_sync(0xffffffffu, posAcc0, o);
        posAcc1 += __shfl_xor_sync(0xffffffffu, posAcc1, o);
        negAcc0 += __shfl_xor_sync(0xffffffffu, negAcc0, o);
        negAcc1 += __shfl_xor_sync(0xffffffffu, negAcc1, o);
    }
    if ((l & 3) == 0) {
        atomicAdd(&g_pos[gr0], posAcc0);
        atomicAdd(&g_neg[gr0], negAcc0);
        atomicAdd(&g_pos[gr1], posAcc1);
        atomicAdd(&g_neg[gr1], negAcc1);
    }

    // ---- pass 2 (off-diag): rows in J, masks (J,I), exp from eT ----
    if (!isDiag) {
        __syncthreads();   // eT fully written
        const int hr0 = j0 + il0, hr1 = j0 + il1;
        float p20 = 0.f, p21 = 0.f, n20 = 0.f, n21 = 0.f;
#pragma unroll
        for (int nf = 0; nf < 16; nf++) {
            int icl = nf * 8 + (l & 3) * 2;
            int ic = m0 + icl;
            int2 P0 = *(const int2*)(pm + (size_t)hr0 * N + ic);
            int2 Q0 = *(const int2*)(nm + (size_t)hr0 * N + ic);
            int2 P1 = *(const int2*)(pm + (size_t)hr1 * N + ic);
            int2 Q1 = *(const int2*)(nm + (size_t)hr1 * N + ic);
            __nv_bfloat162 ea = *(__nv_bfloat162*)(eT + (size_t)il0 * 272 + icl * 2);
            __nv_bfloat162 eb = *(__nv_bfloat162*)(eT + (size_t)il1 * 272 + icl * 2);
            float f00 = __bfloat162float(ea.x), f01 = __bfloat162float(ea.y);
            float f10 = __bfloat162float(eb.x), f11 = __bfloat162float(eb.y);
            p20 = fmaf(f00, (float)P0.x, fmaf(f01, (float)P0.y, p20));
            n20 = fmaf(f00, (float)Q0.x, fmaf(f01, (float)Q0.y, n20));
            p21 = fmaf(f10, (float)P1.x, fmaf(f11, (float)P1.y, p21));
            n21 = fmaf(f10, (float)Q1.x, fmaf(f11, (float)Q1.y, n21));
        }
#pragma unroll
        for (int o = 1; o < 4; o <<= 1) {
            p20 += __shfl_xor_sync(0xffffffffu, p20, o);
            p21 += __shfl_xor_sync(0xffffffffu, p21, o);
            n20 += __shfl_xor_sync(0xffffffffu, n20, o);
            n21 += __shfl_xor_sync(0xffffffffu, n21, o);
        }
        if ((l & 3) == 0) {
            atomicAdd(&g_pos[hr0], p20);
            atomicAdd(&g_neg[hr0], n20);
            atomicAdd(&g_pos[hr1], p21);
            atomicAdd(&g_neg[hr1], n21);
        }
    }
}

// ---------------------------------------------------------------------------
// Kernel 3: final loss reduction. One block.
// ---------------------------------------------------------------------------
__global__ void loss_kernel(float* __restrict__ out) {
    __shared__ double sred[32];
    double s = 0.0;
    for (int r = threadIdx.x; r < N; r += blockDim.x) {
        float pos = g_pos[r];
        float neg = g_neg[r];
        s += (double)logf(pos / (pos + neg));
    }
#pragma unroll
    for (int o = 16; o > 0; o >>= 1) s += __shfl_xor_sync(0xffffffffu, s, o);
    int warp = threadIdx.x >> 5, lane = threadIdx.x & 31;
    if (lane == 0) sred[warp] = s;
    __syncthreads();
    if (warp == 0) {
        s = (lane < (int)(blockDim.x >> 5)) ? sred[lane] : 0.0;
#pragma unroll
        for (int o = 16; o > 0; o >>= 1) s += __shfl_xor_sync(0xffffffffu, s, o);
        if (lane == 0) out[0] = (float)(-s / (double)N);
    }
}

extern "C" void kernel_launch(void* const* d_in, const int* in_sizes, int n_in,
                              void* d_out, int out_size) {
    const float* features = (const float*)d_in[0];
    const int* pos_mask = (const int*)d_in[1];
    const int* neg_mask = (const int*)d_in[2];
    float* out = (float*)d_out;

    cudaFuncSetAttribute(simloss_sym, cudaFuncAttributeMaxDynamicSharedMemorySize,
                         SMEM_BYTES);

    normalize_kernel<<<N / 8, 256>>>(features);
    simloss_sym<<<NPAIRS, 256, SMEM_BYTES>>>(pos_mask, neg_mask);
    loss_kernel<<<1, 1024>>>(out);
}

// round 5
// speedup vs baseline: 1.3370x; 1.0327x over previous
#include <cuda_runtime.h>
#include <cuda_bf16.h>
#include <cstdint>

#define N 8192
#define D 128
#define NT 64
#define NPAIRS 2080
#define LDS 136                  // feature tile smem row stride (bf16)
#define FN_SCALE 4.539815982f    // sqrt(log2(e)/0.07)

// dynamic smem layout (bytes)
#define AS_OFF 0u                // A tile 128x136 bf16 (34816); reused as eT
#define BS_OFF 34816u            // B tile (34816)
#define P_OFF  69632u            // pos mask block: 128 rows x 136 words (69632)
#define Q_OFF  139264u           // neg mask block (69632)
#define MROW   544u              // mask smem row stride bytes (136 words)
#define SMEM_BYTES 208896

#define NTHREADS 512

__device__ __nv_bfloat16 g_fn[N * D];
__device__ float g_pos[N];
__device__ float g_neg[N];

__device__ __forceinline__ float ex2f(float x) {
    float y;
    asm("ex2.approx.ftz.f32 %0, %1;" : "=f"(y) : "f"(x));
    return y;
}

__device__ __forceinline__ void prefetch_l2(const void* p) {
    asm volatile("prefetch.global.L2 [%0];" :: "l"(p));
}

__device__ __forceinline__ void mma16816(float d[4], const uint32_t a[4],
                                         uint32_t b0, uint32_t b1) {
    asm volatile(
        "mma.sync.aligned.m16n8k16.row.col.f32.bf16.bf16.f32 "
        "{%0,%1,%2,%3}, {%4,%5,%6,%7}, {%8,%9}, {%0,%1,%2,%3};"
        : "+f"(d[0]), "+f"(d[1]), "+f"(d[2]), "+f"(d[3])
        : "r"(a[0]), "r"(a[1]), "r"(a[2]), "r"(a[3]), "r"(b0), "r"(b1));
}

// async copy of one 128x128 bf16 tile (row-major, D=128) into padded smem
__device__ __forceinline__ void copy_tile_async(uint32_t sbase,
                                                const __nv_bfloat16* __restrict__ src,
                                                int tid) {
#pragma unroll
    for (int k = 0; k < 4; k++) {
        int i = tid + k * NTHREADS;       // 0..2047 16B chunks
        int r = i >> 4, c = i & 15;
        uint32_t dst = sbase + (uint32_t)((r * LDS + c * 8) * 2);
        const void* s = src + (size_t)r * D + c * 8;
        asm volatile("cp.async.cg.shared.global [%0], [%1], 16;"
                     :: "r"(dst), "l"(s));
    }
}

// async copy of one 128x128 int32 mask block into padded smem (stride MROW)
__device__ __forceinline__ void copy_mask_async(uint32_t dstb,
                                                const int* __restrict__ src,
                                                int row0, int col0, int tid) {
#pragma unroll
    for (int k = 0; k < 8; k++) {
        int i = tid + k * NTHREADS;       // 0..4095 16B chunks
        int r = i >> 5, ch = i & 31;
        uint32_t dst = dstb + (uint32_t)r * MROW + (uint32_t)ch * 16;
        const void* s = src + (size_t)(row0 + r) * N + col0 + ch * 4;
        asm volatile("cp.async.cg.shared.global [%0], [%1], 16;"
                     :: "r"(dst), "l"(s));
    }
}

// L2-prefetch both masks' 128x128 block at (rows r0, cols c0)
__device__ __forceinline__ void prefetch_mask_block(const int* __restrict__ pm,
                                                    const int* __restrict__ nm,
                                                    int r0, int c0, int tid) {
#pragma unroll
    for (int i = 0; i < 2; i++) {
        int L = tid + i * NTHREADS;       // 0..1023 lines
        const int* msk = (L & 512) ? nm : pm;
        int r = (L >> 2) & 127;
        int seg = L & 3;
        prefetch_l2(msk + (size_t)(r0 + r) * N + c0 + seg * 32);
    }
}

// ---------------------------------------------------------------------------
// Kernel 1: L2-normalize rows (exp scale folded) + zero accumulators.
// ---------------------------------------------------------------------------
__global__ void normalize_kernel(const float* __restrict__ f) {
    int z = blockIdx.x * 256 + threadIdx.x;
    if (z < N) g_pos[z] = 0.f;
    else if (z < 2 * N) g_neg[z - N] = 0.f;

    int warp = threadIdx.x >> 5, lane = threadIdx.x & 31;
    int row = blockIdx.x * 8 + warp;
    const float4 v = ((const float4*)(f + (size_t)row * D))[lane];
    float ss = v.x * v.x + v.y * v.y + v.z * v.z + v.w * v.w;
#pragma unroll
    for (int o = 16; o > 0; o >>= 1) ss += __shfl_xor_sync(0xffffffffu, ss, o);
    float rinv = FN_SCALE / fmaxf(sqrtf(ss), 1e-8f);
    union { __nv_bfloat16 h[4]; uint2 u; } pack;
    pack.h[0] = __float2bfloat16_rn(v.x * rinv);
    pack.h[1] = __float2bfloat16_rn(v.y * rinv);
    pack.h[2] = __float2bfloat16_rn(v.z * rinv);
    pack.h[3] = __float2bfloat16_rn(v.w * rinv);
    ((uint2*)(g_fn + (size_t)row * D))[lane] = pack.u;
}

// ---------------------------------------------------------------------------
// Kernel 2: symmetric Gram tile, masks streamed to smem under the MMA.
// 512 threads = 16 warps: warp w -> rows (w&7)*16..+16, col half (w>>3)*64.
// ---------------------------------------------------------------------------
__global__ __launch_bounds__(NTHREADS, 1) void simloss_sym(const int* __restrict__ pm,
                                                           const int* __restrict__ nm) {
    extern __shared__ __align__(16) char smem[];
    const uint32_t base = (uint32_t)__cvta_generic_to_shared(smem);
    const int tid = threadIdx.x;
    const int w = tid >> 5, l = tid & 31;
    const int wr = w & 7, wc = w >> 3;

    // ---- decode triangular pair index ----
    int k = blockIdx.x;
    int I = (int)((129.0f - sqrtf(16641.0f - 8.0f * (float)k)) * 0.5f);
    while ((I * (129 - I)) / 2 > k) I--;
    while (((I + 1) * (128 - I)) / 2 <= k) I++;
    const int J = I + (k - (I * (129 - I)) / 2);
    const int m0 = I * 128, j0 = J * 128;
    const bool isDiag = (I == J);

    // warm L2 for pass-2 masks (transposed block) while pass-1 streams to smem
    if (!isDiag) prefetch_mask_block(pm, nm, j0, m0, tid);

    // feature tiles (group A) then pass-1 masks (group B)
    copy_tile_async(base + AS_OFF, g_fn + (size_t)m0 * D, tid);
    copy_tile_async(base + BS_OFF, g_fn + (size_t)j0 * D, tid);
    asm volatile("cp.async.commit_group;");
    copy_mask_async(base + P_OFF, pm, m0, j0, tid);
    copy_mask_async(base + Q_OFF, nm, m0, j0, tid);
    asm volatile("cp.async.commit_group;");

    asm volatile("cp.async.wait_group 1;");   // tiles ready; masks in flight
    __syncthreads();

    // ---- A frags ----
    uint32_t a[8][4];
    {
        int ar = wr * 16 + (l & 15);
        int ac = (l >> 4) * 8;
#pragma unroll
        for (int ks = 0; ks < 8; ks++) {
            uint32_t addr = base + AS_OFF + (uint32_t)((ar * LDS + ks * 16 + ac) * 2);
            asm volatile(
                "ldmatrix.sync.aligned.m8n8.x4.shared.b16 {%0,%1,%2,%3}, [%4];"
                : "=r"(a[ks][0]), "=r"(a[ks][1]), "=r"(a[ks][2]), "=r"(a[ks][3])
                : "r"(addr));
        }
    }

    // ---- MMA: this warp's 16 rows x 64 cols (mask cp.async drains underneath) ----
    float acc[8][4];
#pragma unroll
    for (int i = 0; i < 8; i++) {
        acc[i][0] = 0.f; acc[i][1] = 0.f; acc[i][2] = 0.f; acc[i][3] = 0.f;
    }
    const int brow = (l >> 4) * 8 + (l & 7);
    const int bcol = ((l >> 3) & 1) * 8;
#pragma unroll
    for (int ks = 0; ks < 8; ks++) {
#pragma unroll
        for (int nf2 = 0; nf2 < 4; nf2++) {
            uint32_t addr = base + BS_OFF +
                (uint32_t)((((wc * 64 + nf2 * 16 + brow)) * LDS + ks * 16 + bcol) * 2);
            uint32_t b0, b1, b2, b3;
            asm volatile(
                "ldmatrix.sync.aligned.m8n8.x4.shared.b16 {%0,%1,%2,%3}, [%4];"
                : "=r"(b0), "=r"(b1), "=r"(b2), "=r"(b3)
                : "r"(addr));
            mma16816(acc[nf2 * 2], a[ks], b0, b1);
            mma16816(acc[nf2 * 2 + 1], a[ks], b2, b3);
        }
    }

    asm volatile("cp.async.wait_group 0;");   // pass-1 masks landed
    __syncthreads();                          // + all warps done with As/Bs

    // ---- pass 1: rows in I, masks (I,J) from smem; write eT for pass 2 ----
    char* eT = smem;                          // overlays As, [jcol][irow], 272B rows
    const int il0 = wr * 16 + (l >> 2), il1 = il0 + 8;
    const int gr0 = m0 + il0, gr1 = m0 + il1;
    float pA0 = 0.f, pA1 = 0.f, nA0 = 0.f, nA1 = 0.f;

#pragma unroll
    for (int nf = 0; nf < 8; nf++) {
        const int jcl = wc * 64 + nf * 8 + (l & 3) * 2;      // col in J block
        uint32_t mp = base + P_OFF + (uint32_t)il0 * MROW + (uint32_t)jcl * 4;
        uint32_t mq = base + Q_OFF + (uint32_t)il0 * MROW + (uint32_t)jcl * 4;
        int2 P0, Q0, P1, Q1;
        asm volatile("ld.shared.v2.b32 {%0,%1}, [%2];" : "=r"(P0.x), "=r"(P0.y) : "r"(mp));
        asm volatile("ld.shared.v2.b32 {%0,%1}, [%2];" : "=r"(Q0.x), "=r"(Q0.y) : "r"(mq));
        asm volatile("ld.shared.v2.b32 {%0,%1}, [%2];" : "=r"(P1.x), "=r"(P1.y) : "r"(mp + 8 * MROW));
        asm volatile("ld.shared.v2.b32 {%0,%1}, [%2];" : "=r"(Q1.x), "=r"(Q1.y) : "r"(mq + 8 * MROW));

        float e00 = ex2f(acc[nf][0]);
        float e01 = ex2f(acc[nf][1]);
        float e10 = ex2f(acc[nf][2]);
        float e11 = ex2f(acc[nf][3]);

        if (!isDiag) {
            *(__nv_bfloat16*)(eT + (size_t)jcl * 272 + il0 * 2) = __float2bfloat16_rn(e00);
            *(__nv_bfloat16*)(eT + (size_t)(jcl + 1) * 272 + il0 * 2) = __float2bfloat16_rn(e01);
            *(__nv_bfloat16*)(eT + (size_t)jcl * 272 + il1 * 2) = __float2bfloat16_rn(e10);
            *(__nv_bfloat16*)(eT + (size_t)(jcl + 1) * 272 + il1 * 2) = __float2bfloat16_rn(e11);
        } else {
            const int jc = j0 + jcl;
            if (gr0 == jc)     { P0.x = 0; Q0.x = 0; }
            if (gr0 == jc + 1) { P0.y = 0; Q0.y = 0; }
            if (gr1 == jc)     { P1.x = 0; Q1.x = 0; }
            if (gr1 == jc + 1) { P1.y = 0; Q1.y = 0; }
        }
        pA0 = fmaf(e00, (float)P0.x, fmaf(e01, (float)P0.y, pA0));
        nA0 = fmaf(e00, (float)Q0.x, fmaf(e01, (float)Q0.y, nA0));
        pA1 = fmaf(e10, (float)P1.x, fmaf(e11, (float)P1.y, pA1));
        nA1 = fmaf(e10, (float)Q1.x, fmaf(e11, (float)Q1.y, nA1));
    }

#pragma unroll
    for (int o = 1; o < 4; o <<= 1) {
        pA0 += __shfl_xor_sync(0xffffffffu, pA0, o);
        pA1 += __shfl_xor_sync(0xffffffffu, pA1, o);
        nA0 += __shfl_xor_sync(0xffffffffu, nA0, o);
        nA1 += __shfl_xor_sync(0xffffffffu, nA1, o);
    }
    if ((l & 3) == 0) {
        atomicAdd(&g_pos[gr0], pA0);
        atomicAdd(&g_neg[gr0], nA0);
        atomicAdd(&g_pos[gr1], pA1);
        atomicAdd(&g_neg[gr1], nA1);
    }

    // ---- pass 2 (off-diag): rows in J, masks (J,I), exp from eT ----
    if (!isDiag) {
        __syncthreads();    // pass-1 smem reads + eT writes complete
        copy_mask_async(base + P_OFF, pm, j0, m0, tid);
        copy_mask_async(base + Q_OFF, nm, j0, m0, tid);
        asm volatile("cp.async.commit_group;");
        asm volatile("cp.async.wait_group 0;");
        __syncthreads();

        const int hr0 = j0 + il0, hr1 = j0 + il1;
        float p20 = 0.f, p21 = 0.f, n20 = 0.f, n21 = 0.f;
#pragma unroll
        for (int nf = 0; nf < 8; nf++) {
            const int icl = wc * 64 + nf * 8 + (l & 3) * 2;  // col in I block
            uint32_t mp = base + P_OFF + (uint32_t)il0 * MROW + (uint32_t)icl * 4;
            uint32_t mq = base + Q_OFF + (uint32_t)il0 * MROW + (uint32_t)icl * 4;
            int2 P0, Q0, P1, Q1;
            asm volatile("ld.shared.v2.b32 {%0,%1}, [%2];" : "=r"(P0.x), "=r"(P0.y) : "r"(mp));
            asm volatile("ld.shared.v2.b32 {%0,%1}, [%2];" : "=r"(Q0.x), "=r"(Q0.y) : "r"(mq));
            asm volatile("ld.shared.v2.b32 {%0,%1}, [%2];" : "=r"(P1.x), "=r"(P1.y) : "r"(mp + 8 * MROW));
            asm volatile("ld.shared.v2.b32 {%0,%1}, [%2];" : "=r"(Q1.x), "=r"(Q1.y) : "r"(mq + 8 * MROW));

            __nv_bfloat162 ea = *(__nv_bfloat162*)(eT + (size_t)il0 * 272 + icl * 2);
            __nv_bfloat162 eb = *(__nv_bfloat162*)(eT + (size_t)il1 * 272 + icl * 2);
            float f00 = __bfloat162float(ea.x), f01 = __bfloat162float(ea.y);
            float f10 = __bfloat162float(eb.x), f11 = __bfloat162float(eb.y);
            p20 = fmaf(f00, (float)P0.x, fmaf(f01, (float)P0.y, p20));
            n20 = fmaf(f00, (float)Q0.x, fmaf(f01, (float)Q0.y, n20));
            p21 = fmaf(f10, (float)P1.x, fmaf(f11, (float)P1.y, p21));
            n21 = fmaf(f10, (float)Q1.x, fmaf(f11, (float)Q1.y, n21));
        }
#pragma unroll
        for (int o = 1; o < 4; o <<= 1) {
            p20 += __shfl_xor_sync(0xffffffffu, p20, o);
            p21 += __shfl_xor_sync(0xffffffffu, p21, o);
            n20 += __shfl_xor_sync(0xffffffffu, n20, o);
            n21 += __shfl_xor_sync(0xffffffffu, n21, o);
        }
        if ((l & 3) == 0) {
            atomicAdd(&g_pos[hr0], p20);
            atomicAdd(&g_neg[hr0], n20);
            atomicAdd(&g_pos[hr1], p21);
            atomicAdd(&g_neg[hr1], n21);
        }
    }
}

// ---------------------------------------------------------------------------
// Kernel 3: final loss reduction. One block.
// ---------------------------------------------------------------------------
__global__ void loss_kernel(float* __restrict__ out) {
    __shared__ double sred[32];
    double s = 0.0;
    for (int r = threadIdx.x; r < N; r += blockDim.x) {
        float pos = g_pos[r];
        float neg = g_neg[r];
        s += (double)logf(pos / (pos + neg));
    }
#pragma unroll
    for (int o = 16; o > 0; o >>= 1) s += __shfl_xor_sync(0xffffffffu, s, o);
    int warp = threadIdx.x >> 5, lane = threadIdx.x & 31;
    if (lane == 0) sred[warp] = s;
    __syncthreads();
    if (warp == 0) {
        s = (lane < (int)(blockDim.x >> 5)) ? sred[lane] : 0.0;
#pragma unroll
        for (int o = 16; o > 0; o >>= 1) s += __shfl_xor_sync(0xffffffffu, s, o);
        if (lane == 0) out[0] = (float)(-s / (double)N);
    }
}

extern "C" void kernel_launch(void* const* d_in, const int* in_sizes, int n_in,
                              void* d_out, int out_size) {
    const float* features = (const float*)d_in[0];
    const int* pos_mask = (const int*)d_in[1];
    const int* neg_mask = (const int*)d_in[2];
    float* out = (float*)d_out;

    cudaFuncSetAttribute(simloss_sym, cudaFuncAttributeMaxDynamicSharedMemorySize,
                         SMEM_BYTES);

    normalize_kernel<<<N / 8, 256>>>(features);
    simloss_sym<<<NPAIRS, NTHREADS, SMEM_BYTES>>>(pos_mask, neg_mask);
    loss_kernel<<<1, 1024>>>(out);
}

// round 6
// speedup vs baseline: 1.4402x; 1.0772x over previous
#include <cuda_runtime.h>
#include <cuda_bf16.h>
#include <cstdint>

#define N 8192
#define D 128
#define NPAIRS 2080
#define LDS 136                  // feature tile smem row stride (bf16)
#define FN_SCALE 4.539815982f    // sqrt(log2(e)/0.07)

// dynamic smem layout (bytes)
#define AS_OFF 0u                // A tile 128x136 bf16 (34816); reused as eT
#define BS_OFF 34816u            // B tile (34816)
#define M0_OFF 69632u            // half-0 mask buffer: P(64x544) + Q(64x544)
#define M1_OFF 139264u           // half-1 mask buffer
#define MHALF  34816u            // Q offset within a buffer
#define MROW   544u              // mask smem row stride bytes (136 words)
#define SMEM_BYTES 208896

#define NTHREADS 512

__device__ __nv_bfloat16 g_fn[N * D];
__device__ float g_pos[N];
__device__ float g_neg[N];

__device__ __forceinline__ float ex2f(float x) {
    float y;
    asm("ex2.approx.ftz.f32 %0, %1;" : "=f"(y) : "f"(x));
    return y;
}

__device__ __forceinline__ void prefetch_l2(const void* p) {
    asm volatile("prefetch.global.L2 [%0];" :: "l"(p));
}

__device__ __forceinline__ void barh(int h) {
    asm volatile("bar.sync %0, 256;" :: "r"(h + 1) : "memory");
}

__device__ __forceinline__ void mma16816(float d[4], const uint32_t a[4],
                                         uint32_t b0, uint32_t b1) {
    asm volatile(
        "mma.sync.aligned.m16n8k16.row.col.f32.bf16.bf16.f32 "
        "{%0,%1,%2,%3}, {%4,%5,%6,%7}, {%8,%9}, {%0,%1,%2,%3};"
        : "+f"(d[0]), "+f"(d[1]), "+f"(d[2]), "+f"(d[3])
        : "r"(a[0]), "r"(a[1]), "r"(a[2]), "r"(a[3]), "r"(b0), "r"(b1));
}

// async copy of one 128x128 bf16 tile (row-major, D=128) into padded smem
__device__ __forceinline__ void copy_tile_async(uint32_t sbase,
                                                const __nv_bfloat16* __restrict__ src,
                                                int tid) {
#pragma unroll
    for (int k = 0; k < 4; k++) {
        int i = tid + k * NTHREADS;       // 0..2047 16B chunks
        int r = i >> 4, c = i & 15;
        uint32_t dst = sbase + (uint32_t)((r * LDS + c * 8) * 2);
        const void* s = src + (size_t)r * D + c * 8;
        asm volatile("cp.async.cg.shared.global [%0], [%1], 16;"
                     :: "r"(dst), "l"(s));
    }
}

// copy both masks' 64-row x 128-col block into this half's buffer (256 threads)
__device__ __forceinline__ void copy_mask_half(uint32_t mb,
                                               const int* __restrict__ pm,
                                               const int* __restrict__ nm,
                                               int row0, int col0, int tloc) {
#pragma unroll
    for (int k = 0; k < 16; k++) {
        int i = tloc + k * 256;           // 0..4095 16B chunks
        const int* mp = (i & 2048) ? nm : pm;
        uint32_t moff = (i & 2048) ? MHALF : 0u;
        int r = (i >> 5) & 63, ch = i & 31;
        uint32_t dst = mb + moff + (uint32_t)r * MROW + (uint32_t)ch * 16;
        const void* s = mp + (size_t)(row0 + r) * N + col0 + ch * 4;
        asm volatile("cp.async.cg.shared.global [%0], [%1], 16;"
                     :: "r"(dst), "l"(s));
    }
}

// L2-prefetch both masks' 128x128 block at (rows r0, cols c0)
__device__ __forceinline__ void prefetch_mask_block(const int* __restrict__ pm,
                                                    const int* __restrict__ nm,
                                                    int r0, int c0, int tid) {
#pragma unroll
    for (int i = 0; i < 2; i++) {
        int L = tid + i * NTHREADS;       // 0..1023 lines
        const int* msk = (L & 512) ? nm : pm;
        int r = (L >> 2) & 127;
        int seg = L & 3;
        prefetch_l2(msk + (size_t)(r0 + r) * N + c0 + seg * 32);
    }
}

// ---------------------------------------------------------------------------
// Kernel 1: L2-normalize rows (exp scale folded) + zero accumulators.
// ---------------------------------------------------------------------------
__global__ void normalize_kernel(const float* __restrict__ f) {
    int z = blockIdx.x * 256 + threadIdx.x;
    if (z < N) g_pos[z] = 0.f;
    else if (z < 2 * N) g_neg[z - N] = 0.f;

    int warp = threadIdx.x >> 5, lane = threadIdx.x & 31;
    int row = blockIdx.x * 8 + warp;
    const float4 v = ((const float4*)(f + (size_t)row * D))[lane];
    float ss = v.x * v.x + v.y * v.y + v.z * v.z + v.w * v.w;
#pragma unroll
    for (int o = 16; o > 0; o >>= 1) ss += __shfl_xor_sync(0xffffffffu, ss, o);
    float rinv = FN_SCALE / fmaxf(sqrtf(ss), 1e-8f);
    union { __nv_bfloat16 h[4]; uint2 u; } pack;
    pack.h[0] = __float2bfloat16_rn(v.x * rinv);
    pack.h[1] = __float2bfloat16_rn(v.y * rinv);
    pack.h[2] = __float2bfloat16_rn(v.z * rinv);
    pack.h[3] = __float2bfloat16_rn(v.w * rinv);
    ((uint2*)(g_fn + (size_t)row * D))[lane] = pack.u;
}

// ---------------------------------------------------------------------------
// Kernel 2: symmetric Gram tile with split-half mask pipeline.
// Warps 0-7 (threads 0-255): rows 0-63, buffer M0. Warps 8-15: rows 64-127, M1.
// Warp w: row block wr = w>>1 (16 rows), col half wc = w&1 (64 cols).
// ---------------------------------------------------------------------------
__global__ __launch_bounds__(NTHREADS, 1) void simloss_sym(const int* __restrict__ pm,
                                                           const int* __restrict__ nm) {
    extern __shared__ __align__(16) char smem[];
    const uint32_t base = (uint32_t)__cvta_generic_to_shared(smem);
    const int tid = threadIdx.x;
    const int w = tid >> 5, l = tid & 31;
    const int wr = w >> 1, wc = w & 1;
    const int h = tid >> 8;               // half id (0: warps 0-7, 1: warps 8-15)
    const int tloc = tid & 255;
    const uint32_t MB = base + (h ? M1_OFF : M0_OFF);

    // ---- decode triangular pair index ----
    int k = blockIdx.x;
    int I = (int)((129.0f - sqrtf(16641.0f - 8.0f * (float)k)) * 0.5f);
    while ((I * (129 - I)) / 2 > k) I--;
    while (((I + 1) * (128 - I)) / 2 <= k) I++;
    const int J = I + (k - (I * (129 - I)) / 2);
    const int m0 = I * 128, j0 = J * 128;
    const bool isDiag = (I == J);

    // warm L2 for pass-2 masks while pass-1 streams into smem
    if (!isDiag) prefetch_mask_block(pm, nm, j0, m0, tid);

    // feature tiles (group 0) then this half's pass-1 masks (group 1)
    copy_tile_async(base + AS_OFF, g_fn + (size_t)m0 * D, tid);
    copy_tile_async(base + BS_OFF, g_fn + (size_t)j0 * D, tid);
    asm volatile("cp.async.commit_group;");
    copy_mask_half(MB, pm, nm, m0 + h * 64, j0, tloc);
    asm volatile("cp.async.commit_group;");

    asm volatile("cp.async.wait_group 1;");   // tiles ready; masks in flight
    __syncthreads();

    // ---- A frags ----
    uint32_t a[8][4];
    {
        int ar = wr * 16 + (l & 15);
        int ac = (l >> 4) * 8;
#pragma unroll
        for (int ks = 0; ks < 8; ks++) {
            uint32_t addr = base + AS_OFF + (uint32_t)((ar * LDS + ks * 16 + ac) * 2);
            asm volatile(
                "ldmatrix.sync.aligned.m8n8.x4.shared.b16 {%0,%1,%2,%3}, [%4];"
                : "=r"(a[ks][0]), "=r"(a[ks][1]), "=r"(a[ks][2]), "=r"(a[ks][3])
                : "r"(addr));
        }
    }
    __syncthreads();   // all frag reads of As done before eT overlays it

    // ---- MMA: 16 rows x 64 cols per warp; mask stream drains underneath ----
    float acc[8][4];
#pragma unroll
    for (int i = 0; i < 8; i++) {
        acc[i][0] = 0.f; acc[i][1] = 0.f; acc[i][2] = 0.f; acc[i][3] = 0.f;
    }
    const int brow = (l >> 4) * 8 + (l & 7);
    const int bcol = ((l >> 3) & 1) * 8;
#pragma unroll
    for (int ks = 0; ks < 8; ks++) {
#pragma unroll
        for (int nf2 = 0; nf2 < 4; nf2++) {
            uint32_t addr = base + BS_OFF +
                (uint32_t)((((wc * 64 + nf2 * 16 + brow)) * LDS + ks * 16 + bcol) * 2);
            uint32_t b0, b1, b2, b3;
            asm volatile(
                "ldmatrix.sync.aligned.m8n8.x4.shared.b16 {%0,%1,%2,%3}, [%4];"
                : "=r"(b0), "=r"(b1), "=r"(b2), "=r"(b3)
                : "r"(addr));
            mma16816(acc[nf2 * 2], a[ks], b0, b1);
            mma16816(acc[nf2 * 2 + 1], a[ks], b2, b3);
        }
    }

    asm volatile("cp.async.wait_group 0;");   // this half's pass-1 masks landed
    barh(h);

    // ---- pass 1: rows in I (own half), masks (I,J) from smem; write eT ----
    char* eT = smem;                          // overlays As: [jcol][irow], 272B rows
    const int il0 = wr * 16 + (l >> 2), il1 = il0 + 8;
    const int rl0 = il0 & 63;                 // row local to half buffer
    const int gr0 = m0 + il0, gr1 = m0 + il1;
    float pA0 = 0.f, pA1 = 0.f, nA0 = 0.f, nA1 = 0.f;

#pragma unroll
    for (int nf = 0; nf < 8; nf++) {
        const int jcl = wc * 64 + nf * 8 + (l & 3) * 2;      // col in J block
        uint32_t mp = MB + (uint32_t)rl0 * MROW + (uint32_t)jcl * 4;
        uint32_t mq = mp + MHALF;
        int2 P0, Q0, P1, Q1;
        asm volatile("ld.shared.v2.b32 {%0,%1}, [%2];" : "=r"(P0.x), "=r"(P0.y) : "r"(mp));
        asm volatile("ld.shared.v2.b32 {%0,%1}, [%2];" : "=r"(Q0.x), "=r"(Q0.y) : "r"(mq));
        asm volatile("ld.shared.v2.b32 {%0,%1}, [%2];" : "=r"(P1.x), "=r"(P1.y) : "r"(mp + 8 * MROW));
        asm volatile("ld.shared.v2.b32 {%0,%1}, [%2];" : "=r"(Q1.x), "=r"(Q1.y) : "r"(mq + 8 * MROW));

        float e00 = ex2f(acc[nf][0]);
        float e01 = ex2f(acc[nf][1]);
        float e10 = ex2f(acc[nf][2]);
        float e11 = ex2f(acc[nf][3]);

        if (!isDiag) {
            *(__nv_bfloat16*)(eT + (size_t)jcl * 272 + il0 * 2) = __float2bfloat16_rn(e00);
            *(__nv_bfloat16*)(eT + (size_t)(jcl + 1) * 272 + il0 * 2) = __float2bfloat16_rn(e01);
            *(__nv_bfloat16*)(eT + (size_t)jcl * 272 + il1 * 2) = __float2bfloat16_rn(e10);
            *(__nv_bfloat16*)(eT + (size_t)(jcl + 1) * 272 + il1 * 2) = __float2bfloat16_rn(e11);
        } else {
            const int jc = j0 + jcl;
            if (gr0 == jc)     { P0.x = 0; Q0.x = 0; }
            if (gr0 == jc + 1) { P0.y = 0; Q0.y = 0; }
            if (gr1 == jc)     { P1.x = 0; Q1.x = 0; }
            if (gr1 == jc + 1) { P1.y = 0; Q1.y = 0; }
        }
        pA0 = fmaf(e00, (float)P0.x, fmaf(e01, (float)P0.y, pA0));
        nA0 = fmaf(e00, (float)Q0.x, fmaf(e01, (float)Q0.y, nA0));
        pA1 = fmaf(e10, (float)P1.x, fmaf(e11, (float)P1.y, pA1));
        nA1 = fmaf(e10, (float)Q1.x, fmaf(e11, (float)Q1.y, nA1));
    }

#pragma unroll
    for (int o = 1; o < 4; o <<= 1) {
        pA0 += __shfl_xor_sync(0xffffffffu, pA0, o);
        pA1 += __shfl_xor_sync(0xffffffffu, pA1, o);
        nA0 += __shfl_xor_sync(0xffffffffu, nA0, o);
        nA1 += __shfl_xor_sync(0xffffffffu, nA1, o);
    }
    if ((l & 3) == 0) {
        atomicAdd(&g_pos[gr0], pA0);
        atomicAdd(&g_neg[gr0], nA0);
        atomicAdd(&g_pos[gr1], pA1);
        atomicAdd(&g_neg[gr1], nA1);
    }

    barh(h);   // this half fully done reading its mask buffer

    // issue pass-2 mask copy NOW (streams during other half's work + eT sync)
    if (!isDiag) {
        copy_mask_half(MB, pm, nm, j0 + h * 64, m0, tloc);
        asm volatile("cp.async.commit_group;");
    }

    __syncthreads();   // eT fully written by both halves

    // ---- pass 2 (off-diag): rows in J (own half), masks (J,I), exp from eT ----
    if (!isDiag) {
        asm volatile("cp.async.wait_group 0;");
        barh(h);

        const int hr0 = j0 + il0, hr1 = j0 + il1;
        float p20 = 0.f, p21 = 0.f, n20 = 0.f, n21 = 0.f;
#pragma unroll
        for (int nf = 0; nf < 8; nf++) {
            const int icl = wc * 64 + nf * 8 + (l & 3) * 2;  // col in I block
            uint32_t mp = MB + (uint32_t)rl0 * MROW + (uint32_t)icl * 4;
            uint32_t mq = mp + MHALF;
            int2 P0, Q0, P1, Q1;
            asm volatile("ld.shared.v2.b32 {%0,%1}, [%2];" : "=r"(P0.x), "=r"(P0.y) : "r"(mp));
            asm volatile("ld.shared.v2.b32 {%0,%1}, [%2];" : "=r"(Q0.x), "=r"(Q0.y) : "r"(mq));
            asm volatile("ld.shared.v2.b32 {%0,%1}, [%2];" : "=r"(P1.x), "=r"(P1.y) : "r"(mp + 8 * MROW));
            asm volatile("ld.shared.v2.b32 {%0,%1}, [%2];" : "=r"(Q1.x), "=r"(Q1.y) : "r"(mq + 8 * MROW));

            __nv_bfloat162 ea = *(__nv_bfloat162*)(eT + (size_t)il0 * 272 + icl * 2);
            __nv_bfloat162 eb = *(__nv_bfloat162*)(eT + (size_t)il1 * 272 + icl * 2);
            float f00 = __bfloat162float(ea.x), f01 = __bfloat162float(ea.y);
            float f10 = __bfloat162float(eb.x), f11 = __bfloat162float(eb.y);
            p20 = fmaf(f00, (float)P0.x, fmaf(f01, (float)P0.y, p20));
            n20 = fmaf(f00, (float)Q0.x, fmaf(f01, (float)Q0.y, n20));
            p21 = fmaf(f10, (float)P1.x, fmaf(f11, (float)P1.y, p21));
            n21 = fmaf(f10, (float)Q1.x, fmaf(f11, (float)Q1.y, n21));
        }
#pragma unroll
        for (int o = 1; o < 4; o <<= 1) {
            p20 += __shfl_xor_sync(0xffffffffu, p20, o);
            p21 += __shfl_xor_sync(0xffffffffu, p21, o);
            n20 += __shfl_xor_sync(0xffffffffu, n20, o);
            n21 += __shfl_xor_sync(0xffffffffu, n21, o);
        }
        if ((l & 3) == 0) {
            atomicAdd(&g_pos[hr0], p20);
            atomicAdd(&g_neg[hr0], n20);
            atomicAdd(&g_pos[hr1], p21);
            atomicAdd(&g_neg[hr1], n21);
        }
    }
}

// ---------------------------------------------------------------------------
// Kernel 3: final loss reduction. One block.
// ---------------------------------------------------------------------------
__global__ void loss_kernel(float* __restrict__ out) {
    __shared__ double sred[32];
    double s = 0.0;
    for (int r = threadIdx.x; r < N; r += blockDim.x) {
        float pos = g_pos[r];
        float neg = g_neg[r];
        s += (double)logf(pos / (pos + neg));
    }
#pragma unroll
    for (int o = 16; o > 0; o >>= 1) s += __shfl_xor_sync(0xffffffffu, s, o);
    int warp = threadIdx.x >> 5, lane = threadIdx.x & 31;
    if (lane == 0) sred[warp] = s;
    __syncthreads();
    if (warp == 0) {
        s = (lane < (int)(blockDim.x >> 5)) ? sred[lane] : 0.0;
#pragma unroll
        for (int o = 16; o > 0; o >>= 1) s += __shfl_xor_sync(0xffffffffu, s, o);
        if (lane == 0) out[0] = (float)(-s / (double)N);
    }
}

extern "C" void kernel_launch(void* const* d_in, const int* in_sizes, int n_in,
                              void* d_out, int out_size) {
    const float* features = (const float*)d_in[0];
    const int* pos_mask = (const int*)d_in[1];
    const int* neg_mask = (const int*)d_in[2];
    float* out = (float*)d_out;

    cudaFuncSetAttribute(simloss_sym, cudaFuncAttributeMaxDynamicSharedMemorySize,
                         SMEM_BYTES);

    normalize_kernel<<<N / 8, 256>>>(features);
    simloss_sym<<<NPAIRS, NTHREADS, SMEM_BYTES>>>(pos_mask, neg_mask);
    loss_kernel<<<1, 1024>>>(out);
}